// round 14
// baseline (speedup 1.0000x reference)
#include <cuda_runtime.h>
#include <math.h>

typedef unsigned long long ull;

#define N_NODES 100000
#define N_EDGES 1600000
#define NPAD    100096      // 782 * 128
#define DIM     128
#define OUTD    40
#define BCAP    128         // bucket capacity (max degree ~45 for Poisson(16))
#define EPSF    1e-12f
#define GEMM_BLOCKS 782     // NPAD / 128

// smem float-index offsets for k_gemm1p (dynamic smem, 167936 bytes)
#define WL_OFF  0            // 128 j x stride 132  (67584 B)
#define WR_OFF  16896        // 128 j x stride 132  (67584 B)
#define AX_OFF  33792        // 32 warps x 2 buffers x 128 floats (32768 B)
#define SH_OFF  0            // overlay: 128 rows x stride 132
#define W2_OFF  16896        // overlay: 96 j x stride 132
#define SMEM_BYTES 167936

// packed dual-FMA (Blackwell f32x2): d.lo += a.lo*b.lo, d.hi += a.hi*b.hi
__device__ __forceinline__ void FMA2(ull& d, ull a, ull b) {
    asm("fma.rn.f32x2 %0, %1, %2, %0;" : "+l"(d) : "l"(a), "l"(b));
}
__device__ __forceinline__ float unpack_sum(ull v) {
    return __uint_as_float((unsigned)v) + __uint_as_float((unsigned)(v >> 32));
}
// 16B async copy global->shared; szbytes<16 zero-fills the remainder
__device__ __forceinline__ void cpa16(unsigned dst, const void* src, int szbytes) {
    asm volatile("cp.async.cg.shared.global [%0], [%1], 16, %2;"
                 :: "r"(dst), "l"(src), "r"(szbytes));
}
#define CP_COMMIT() asm volatile("cp.async.commit_group;")
#define CP_WAIT(n)  asm volatile("cp.async.wait_group %0;" :: "n"(n))

// ------------------------- scratch (static, no allocs) -------------------------
__device__ int   g_is64;
__device__ int   g_cnt[N_NODES];
__device__ int   g_bkt[(size_t)N_NODES * BCAP];   // fixed-capacity edge buckets
__device__ float g_agg[(size_t)NPAD * DIM];       // pad rows stay 0
__device__ float g_p[(size_t)NPAD * OUTD];        // h @ W2_l^T (pad rows junk, never read)
__device__ float g_hr[(size_t)NPAD * OUTD];       // h @ W2_r^T

// ------------------------- init: zero counters + dtype detect -----------------
__global__ void k_init(const unsigned* __restrict__ p) {
    int i = blockIdx.x * blockDim.x + threadIdx.x;
    if (i < N_NODES) g_cnt[i] = 0;
    if (blockIdx.x == 0) {
        __shared__ int flag;
        if (threadIdx.x == 0) flag = 0;
        __syncthreads();
        int any = 0;
        for (int j = threadIdx.x; j < 4096; j += 256)
            if (p[2 * j + 1] != 0u) any = 1;
        if (any) atomicOr(&flag, 1);
        __syncthreads();
        if (threadIdx.x == 0) g_is64 = flag ? 0 : 1;  // all-zero high words => int64
    }
}

// ------------- single-pass scatter into fixed-capacity buckets ----------------
__global__ void k_bucket(const void* __restrict__ eiv) {
    int e = blockIdx.x * blockDim.x + threadIdx.x;
    if (e >= N_EDGES) return;
    int s, d;
    if (g_is64) {
        const long long* ei = (const long long*)eiv;
        s = (int)ei[e]; d = (int)ei[N_EDGES + e];
    } else {
        const int* ei = (const int*)eiv;
        s = ei[e]; d = ei[N_EDGES + e];
    }
    int pos = atomicAdd(&g_cnt[d], 1);
    if (pos < BCAP) g_bkt[(size_t)d * BCAP + pos] = s;   // guard: memory safety
}

// ------------------------- mean aggregation (128-dim): warp per dst node ------
__global__ void k_agg(const float4* __restrict__ xin) {
    int gt = blockIdx.x * blockDim.x + threadIdx.x;
    int w = gt >> 5, lane = gt & 31;
    if (w >= N_NODES) return;
    int rawcnt = g_cnt[w];
    int cnt = min(rawcnt, BCAP);
    const int* bp = &g_bkt[(size_t)w * BCAP];
    float ax = 0.f, ay = 0.f, az = 0.f, aw = 0.f;
    int e = 0;
    for (; e + 8 <= cnt; e += 8) {
        int s0 = bp[e + 0];
        int s1 = bp[e + 1];
        int s2 = bp[e + 2];
        int s3 = bp[e + 3];
        int s4 = bp[e + 4];
        int s5 = bp[e + 5];
        int s6 = bp[e + 6];
        int s7 = bp[e + 7];
        float4 v0 = xin[(size_t)s0 * 32 + lane];
        float4 v1 = xin[(size_t)s1 * 32 + lane];
        float4 v2 = xin[(size_t)s2 * 32 + lane];
        float4 v3 = xin[(size_t)s3 * 32 + lane];
        float4 v4 = xin[(size_t)s4 * 32 + lane];
        float4 v5 = xin[(size_t)s5 * 32 + lane];
        float4 v6 = xin[(size_t)s6 * 32 + lane];
        float4 v7 = xin[(size_t)s7 * 32 + lane];
        ax += (v0.x + v1.x) + (v2.x + v3.x) + ((v4.x + v5.x) + (v6.x + v7.x));
        ay += (v0.y + v1.y) + (v2.y + v3.y) + ((v4.y + v5.y) + (v6.y + v7.y));
        az += (v0.z + v1.z) + (v2.z + v3.z) + ((v4.z + v5.z) + (v6.z + v7.z));
        aw += (v0.w + v1.w) + (v2.w + v3.w) + ((v4.w + v5.w) + (v6.w + v7.w));
    }
    for (; e + 2 <= cnt; e += 2) {
        int s0 = bp[e + 0];
        int s1 = bp[e + 1];
        float4 v0 = xin[(size_t)s0 * 32 + lane];
        float4 v1 = xin[(size_t)s1 * 32 + lane];
        ax += v0.x + v1.x; ay += v0.y + v1.y;
        az += v0.z + v1.z; aw += v0.w + v1.w;
    }
    if (e < cnt) {
        int s = bp[e];
        float4 v = xin[(size_t)s * 32 + lane];
        ax += v.x; ay += v.y; az += v.z; aw += v.w;
    }
    float di = 1.0f / fmaxf((float)rawcnt, 1.0f);
    float4 r; r.x = ax * di; r.y = ay * di; r.z = az * di; r.w = aw * di;
    ((float4*)g_agg)[(size_t)w * 32 + lane] = r;
}

// -- layer 1: resident-weight dual GEMM + L2norm/relu + in-block projection ----
// 1024 threads (32 warps, 8/SMSP), 1 CTA/SM. Full W1_l/W1_r staged ONCE
// (stride-132, conflict-free LDS.128). Each warp owns 4 rows; A/X tiles
// double-buffered per warp via cp.async (512B/warp buffers).
__global__ __launch_bounds__(1024, 1) void k_gemm1p(const float* __restrict__ x,
                                                    const float* __restrict__ Wl,
                                                    const float* __restrict__ Wr,
                                                    const float* __restrict__ bias,
                                                    const float* __restrict__ W2l,
                                                    const float* __restrict__ W2r) {
    extern __shared__ __align__(16) float sm[];

    int tid = threadIdx.x;
    int rg = tid >> 5, cg = tid & 31;     // 32 warps, warp rg owns rows rg*4..+3
    int rowBase = blockIdx.x * 128;

    const float4* x4 = (const float4*)x;
    const float4* a4 = (const float4*)g_agg;
    const float4* wl4 = (const float4*)Wl;
    const float4* wr4 = (const float4*)Wr;

    // ---- stage full weights once (4096 float4 each) ----
    for (int t = tid; t < 4096; t += 1024) {
        int j = t >> 5, c = t & 31;
        *(float4*)&sm[WL_OFF + j * 132 + c * 4] = wl4[t];
        *(float4*)&sm[WR_OFF + j * 132 + c * 4] = wr4[t];
    }

    ull acc[4][4];
#pragma unroll
    for (int c = 0; c < 4; c++) {
        ull b = (ull)__float_as_uint(bias[cg + 32 * c]);   // lo=bias, hi=0
#pragma unroll
        for (int i = 0; i < 4; i++) acc[i][c] = b;
    }

    // per-warp double buffer: 2 x (sA 64 | sX 64) floats = 1KB
    float* axbuf = &sm[AX_OFF + rg * 256];
    unsigned axsh = (unsigned)__cvta_generic_to_shared(axbuf);
    bool stager = (cg < 16);               // 4 rows x 4 float4 chunks
    int lr = (cg >> 2) & 3, lc = cg & 3;
    int myrow = rowBase + rg * 4 + lr;     // < NPAD; g_agg pad rows are zeros
    int xvalid = (myrow < N_NODES) ? 16 : 0;
    unsigned laneoff = (unsigned)(lr * 64 + lc * 16);

    __syncthreads();                       // weights resident

    // prefetch kt=0 (lanes 0..15)
    if (stager) {
        cpa16(axsh + laneoff, &a4[(size_t)myrow * 32 + lc], 16);
        cpa16(axsh + 256 + laneoff, &x4[(size_t)myrow * 32 + lc], xvalid);
        CP_COMMIT();
    }

    for (int kt = 0; kt < 8; kt++) {
        __syncwarp();                      // prior buffer reads done warp-wide
        if (stager) {
            if (kt < 7) {
                unsigned boff = ((kt + 1) & 1) * 512;
                cpa16(axsh + boff + laneoff,
                      &a4[(size_t)myrow * 32 + (kt + 1) * 4 + lc], 16);
                cpa16(axsh + boff + 256 + laneoff,
                      &x4[(size_t)myrow * 32 + (kt + 1) * 4 + lc], xvalid);
                CP_COMMIT();
                CP_WAIT(1);                // group kt complete
            } else {
                CP_WAIT(0);
            }
        }
        __syncwarp();                      // staging lanes' writes visible

        const float* sA = axbuf + (kt & 1) * 128;
        const float* sX = sA + 64;
#pragma unroll
        for (int kp2 = 0; kp2 < 4; kp2++) {
            int ko = kt * 16 + kp2 * 4;
            ulonglong2 wl[4], wr[4];
#pragma unroll
            for (int c = 0; c < 4; c++) {
                wl[c] = *(const ulonglong2*)&sm[WL_OFF + (cg + 32 * c) * 132 + ko];
                wr[c] = *(const ulonglong2*)&sm[WR_OFF + (cg + 32 * c) * 132 + ko];
            }
#pragma unroll
            for (int i = 0; i < 4; i++) {
                ulonglong2 a  = *(const ulonglong2*)&sA[i * 16 + kp2 * 4];  // bcast
                ulonglong2 xx = *(const ulonglong2*)&sX[i * 16 + kp2 * 4];  // bcast
#pragma unroll
                for (int c = 0; c < 4; c++) {
                    FMA2(acc[i][c], a.x,  wl[c].x);
                    FMA2(acc[i][c], a.y,  wl[c].y);
                    FMA2(acc[i][c], xx.x, wr[c].x);
                    FMA2(acc[i][c], xx.y, wr[c].y);
                }
            }
        }
    }

    __syncthreads();   // all weight reads done; safe to overlay sH / sW2

    // stage combined proj weights C[96 x 128] (rows 0..39=W2l, 40..79=W2r, pad)
    {
        const float4* w2l4 = (const float4*)W2l;
        const float4* w2r4 = (const float4*)W2r;
        for (int t = tid; t < 96 * 32; t += 1024) {
            int j = t >> 5, c = t & 31;
            float4 w = make_float4(0.f, 0.f, 0.f, 0.f);
            if (j < OUTD)          w = w2l4[j * 32 + c];
            else if (j < 2 * OUTD) w = w2r4[(j - OUTD) * 32 + c];
            *(float4*)&sm[W2_OFF + j * 132 + c * 4] = w;
        }
    }

    // epilogue: L2-normalize + relu; h rows are warp-private in sH (stride 132)
#pragma unroll
    for (int i = 0; i < 4; i++) {
        float v[4];
        float ss = 0.f;
#pragma unroll
        for (int c = 0; c < 4; c++) { v[c] = unpack_sum(acc[i][c]); ss += v[c] * v[c]; }
#pragma unroll
        for (int o = 16; o > 0; o >>= 1) ss += __shfl_xor_sync(0xffffffffu, ss, o);
        float scale = 1.0f / fmaxf(sqrtf(ss), EPSF);
#pragma unroll
        for (int c = 0; c < 4; c++)
            sm[SH_OFF + (rg * 4 + i) * 132 + cg + 32 * c] = fmaxf(v[c] * scale, 0.f);
    }

    __syncthreads();   // sW2 visible (sH rows stay warp-private)

    // in-block combined projection: [p | hr] = h @ C^T  (no syncs inside)
    ull pacc[4][3];
#pragma unroll
    for (int i = 0; i < 4; i++) {
        pacc[i][0] = 0ull; pacc[i][1] = 0ull; pacc[i][2] = 0ull;
    }
#pragma unroll
    for (int kt = 0; kt < 8; kt++) {
#pragma unroll
        for (int kp2 = 0; kp2 < 4; kp2++) {
            int ko = kt * 16 + kp2 * 4;
            ulonglong2 w0 = *(const ulonglong2*)&sm[W2_OFF + cg * 132 + ko];
            ulonglong2 w1 = *(const ulonglong2*)&sm[W2_OFF + (cg + 32) * 132 + ko];
            ulonglong2 w2 = *(const ulonglong2*)&sm[W2_OFF + (cg + 64) * 132 + ko];
#pragma unroll
            for (int i = 0; i < 4; i++) {
                ulonglong2 a = *(const ulonglong2*)&sm[SH_OFF + (rg * 4 + i) * 132 + ko];
                FMA2(pacc[i][0], a.x, w0.x); FMA2(pacc[i][0], a.y, w0.y);
                FMA2(pacc[i][1], a.x, w1.x); FMA2(pacc[i][1], a.y, w1.y);
                FMA2(pacc[i][2], a.x, w2.x); FMA2(pacc[i][2], a.y, w2.y);
            }
        }
    }
#pragma unroll
    for (int i = 0; i < 4; i++) {
        int row = rowBase + rg * 4 + i;      // < NPAD always
#pragma unroll
        for (int c = 0; c < 3; c++) {
            int jc = cg + 32 * c;
            float val = unpack_sum(pacc[i][c]);
            if (jc < OUTD)            g_p[(size_t)row * OUTD + jc] = val;
            else if (jc < 2 * OUTD)   g_hr[(size_t)row * OUTD + (jc - OUTD)] = val;
        }
    }
}

// ---- fused layer-2 tail: gather p -> mean -> +b2+hr -> norm/relu/logsoftmax ---
__global__ void k_aggfinal(const float* __restrict__ bias,
                           float* __restrict__ out) {
    int gt = blockIdx.x * blockDim.x + threadIdx.x;
    int w = gt >> 5, lane = gt & 31;
    if (w >= N_NODES) return;
    bool valid = lane < 20;
    float sx = 0.f, sy = 0.f;
    if (valid) {
        const float2* p2 = (const float2*)g_p;
        int rawcnt = g_cnt[w];
        int cnt = min(rawcnt, BCAP);
        const int* bp = &g_bkt[(size_t)w * BCAP];
        int e = 0;
        for (; e + 8 <= cnt; e += 8) {
            int s0 = bp[e + 0];
            int s1 = bp[e + 1];
            int s2 = bp[e + 2];
            int s3 = bp[e + 3];
            int s4 = bp[e + 4];
            int s5 = bp[e + 5];
            int s6 = bp[e + 6];
            int s7 = bp[e + 7];
            float2 v0 = p2[(size_t)s0 * 20 + lane];
            float2 v1 = p2[(size_t)s1 * 20 + lane];
            float2 v2 = p2[(size_t)s2 * 20 + lane];
            float2 v3 = p2[(size_t)s3 * 20 + lane];
            float2 v4 = p2[(size_t)s4 * 20 + lane];
            float2 v5 = p2[(size_t)s5 * 20 + lane];
            float2 v6 = p2[(size_t)s6 * 20 + lane];
            float2 v7 = p2[(size_t)s7 * 20 + lane];
            sx += (v0.x + v1.x) + (v2.x + v3.x) + ((v4.x + v5.x) + (v6.x + v7.x));
            sy += (v0.y + v1.y) + (v2.y + v3.y) + ((v4.y + v5.y) + (v6.y + v7.y));
        }
        for (; e < cnt; e++) {
            int s = bp[e];
            float2 v = p2[(size_t)s * 20 + lane];
            sx += v.x; sy += v.y;
        }
        float di = 1.0f / fmaxf((float)rawcnt, 1.0f);
        float2 h = ((const float2*)g_hr)[(size_t)w * 20 + lane];
        float2 b = ((const float2*)bias)[lane];
        sx = sx * di + b.x + h.x;
        sy = sy * di + b.y + h.y;
    }
    float ss = sx * sx + sy * sy;
#pragma unroll
    for (int o = 16; o > 0; o >>= 1) ss += __shfl_xor_sync(0xffffffffu, ss, o);
    float scale = 1.0f / fmaxf(sqrtf(ss), EPSF);
    sx = fmaxf(sx * scale, 0.f);
    sy = fmaxf(sy * scale, 0.f);
    float m = valid ? fmaxf(sx, sy) : -3.0e38f;
#pragma unroll
    for (int o = 16; o > 0; o >>= 1) m = fmaxf(m, __shfl_xor_sync(0xffffffffu, m, o));
    float p = valid ? (expf(sx - m) + expf(sy - m)) : 0.f;
#pragma unroll
    for (int o = 16; o > 0; o >>= 1) p += __shfl_xor_sync(0xffffffffu, p, o);
    float lse = m + logf(p);
    if (valid) {
        float2 o2 = make_float2(sx - lse, sy - lse);
        *(float2*)&out[(size_t)w * OUTD + 2 * lane] = o2;
    }
}

// ------------------------- launcher -------------------------------------------
extern "C" void kernel_launch(void* const* d_in, const int* in_sizes, int n_in,
                              void* d_out, int out_size) {
    const float* x   = (const float*)d_in[0];
    const void*  ei  = d_in[1];
    const float* W1l = (const float*)d_in[2];
    const float* b1  = (const float*)d_in[3];
    const float* W1r = (const float*)d_in[4];
    const float* W2l = (const float*)d_in[5];
    const float* b2  = (const float*)d_in[6];
    const float* W2r = (const float*)d_in[7];
    float* out = (float*)d_out;

    cudaFuncSetAttribute(k_gemm1p, cudaFuncAttributeMaxDynamicSharedMemorySize,
                         SMEM_BYTES);

    // prep: zero counters + dtype detect, then one-pass bucket scatter
    k_init<<<(N_NODES + 255) / 256, 256>>>((const unsigned*)ei);
    k_bucket<<<(N_EDGES + 255) / 256, 256>>>(ei);

    // layer 1: agg -> resident-weight dual gemm (+norm/relu) with fused proj
    k_agg<<<(N_NODES * 32 + 255) / 256, 256>>>((const float4*)x);
    k_gemm1p<<<GEMM_BLOCKS, 1024, SMEM_BYTES>>>(x, W1l, W1r, b1, W2l, W2r);

    // layer 2 tail: fused gather + epilogue
    k_aggfinal<<<(N_NODES * 32 + 255) / 256, 256>>>(b2, out);
}

// round 15
// speedup vs baseline: 1.5147x; 1.5147x over previous
#include <cuda_runtime.h>
#include <cuda_fp16.h>
#include <math.h>

typedef unsigned long long ull;

#define N_NODES 100000
#define N_EDGES 1600000
#define NPAD    100096      // 782 * 128
#define DIM     128
#define OUTD    40
#define BCAP    128         // bucket capacity (max degree ~45 for Poisson(16))
#define EPSF    1e-12f
#define GEMM_BLOCKS 782     // NPAD / 128

// smem float-index offsets for k_gemm1p (dynamic smem, 167936 bytes)
#define WL_OFF  0            // 128 j x stride 132  (67584 B)
#define WR_OFF  16896        // 128 j x stride 132  (67584 B)
#define AX_OFF  33792        // 16 warps x 2 buffers x 256 floats (32768 B)
#define SH_OFF  0            // overlay: 128 rows x stride 132
#define W2_OFF  16896        // overlay: 96 j x stride 132
#define SMEM_BYTES 167936

// packed dual-FMA (Blackwell f32x2): d.lo += a.lo*b.lo, d.hi += a.hi*b.hi
__device__ __forceinline__ void FMA2(ull& d, ull a, ull b) {
    asm("fma.rn.f32x2 %0, %1, %2, %0;" : "+l"(d) : "l"(a), "l"(b));
}
__device__ __forceinline__ float unpack_sum(ull v) {
    return __uint_as_float((unsigned)v) + __uint_as_float((unsigned)(v >> 32));
}
// 16B async copy global->shared; szbytes<16 zero-fills the remainder
__device__ __forceinline__ void cpa16(unsigned dst, const void* src, int szbytes) {
    asm volatile("cp.async.cg.shared.global [%0], [%1], 16, %2;"
                 :: "r"(dst), "l"(src), "r"(szbytes));
}
#define CP_COMMIT() asm volatile("cp.async.commit_group;")
#define CP_WAIT(n)  asm volatile("cp.async.wait_group %0;" :: "n"(n))

// ------------------------- scratch (static, no allocs) -------------------------
__device__ int    g_is64;
__device__ int    g_cnt[N_NODES];
__device__ int    g_bkt[(size_t)N_NODES * BCAP];  // fixed-capacity edge buckets
__device__ __half g_xh[(size_t)N_NODES * DIM];    // fp16 copy of x (gather source)
__device__ float  g_agg[(size_t)NPAD * DIM];      // pad rows stay 0
__device__ __half g_p[(size_t)NPAD * OUTD];       // h @ W2_l^T, fp16 (gather source)
__device__ float  g_hr[(size_t)NPAD * OUTD];      // h @ W2_r^T

// ------------------------- init: zero counters + dtype detect -----------------
__global__ void k_init(const unsigned* __restrict__ p) {
    int i = blockIdx.x * blockDim.x + threadIdx.x;
    if (i < N_NODES) g_cnt[i] = 0;
    if (blockIdx.x == 0) {
        __shared__ int flag;
        if (threadIdx.x == 0) flag = 0;
        __syncthreads();
        int any = 0;
        for (int j = threadIdx.x; j < 4096; j += 256)
            if (p[2 * j + 1] != 0u) any = 1;
        if (any) atomicOr(&flag, 1);
        __syncthreads();
        if (threadIdx.x == 0) g_is64 = flag ? 0 : 1;  // all-zero high words => int64
    }
}

// ------------------------- fp32 -> fp16 conversion of x ------------------------
__global__ void k_tohalf(const float4* __restrict__ x4) {
    int i = blockIdx.x * blockDim.x + threadIdx.x;      // over N_NODES*32 float4s
    if (i >= N_NODES * 32) return;
    float4 v = x4[i];
    __half2 h0 = __floats2half2_rn(v.x, v.y);
    __half2 h1 = __floats2half2_rn(v.z, v.w);
    uint2 u;
    u.x = *(unsigned*)&h0;
    u.y = *(unsigned*)&h1;
    ((uint2*)g_xh)[i] = u;
}

// ------------- single-pass scatter into fixed-capacity buckets ----------------
__global__ void k_bucket(const void* __restrict__ eiv) {
    int e = blockIdx.x * blockDim.x + threadIdx.x;
    if (e >= N_EDGES) return;
    int s, d;
    if (g_is64) {
        const long long* ei = (const long long*)eiv;
        s = (int)ei[e]; d = (int)ei[N_EDGES + e];
    } else {
        const int* ei = (const int*)eiv;
        s = ei[e]; d = ei[N_EDGES + e];
    }
    int pos = atomicAdd(&g_cnt[d], 1);
    if (pos < BCAP) g_bkt[(size_t)d * BCAP + pos] = s;   // guard: memory safety
}

// ---------- mean aggregation (128-dim, fp16 gather): warp per dst node --------
__device__ __forceinline__ void acc_half4(uint2 u, float& ax, float& ay,
                                          float& az, float& aw) {
    __half2 h0 = *(__half2*)&u.x;
    __half2 h1 = *(__half2*)&u.y;
    float2 f0 = __half22float2(h0);
    float2 f1 = __half22float2(h1);
    ax += f0.x; ay += f0.y; az += f1.x; aw += f1.y;
}

__global__ void k_agg() {
    int gt = blockIdx.x * blockDim.x + threadIdx.x;
    int w = gt >> 5, lane = gt & 31;
    if (w >= N_NODES) return;
    const uint2* xh = (const uint2*)g_xh;    // 32 uint2 per row (4 halves each)
    int rawcnt = g_cnt[w];
    int cnt = min(rawcnt, BCAP);
    const int* bp = &g_bkt[(size_t)w * BCAP];
    float ax = 0.f, ay = 0.f, az = 0.f, aw = 0.f;
    int e = 0;
    for (; e + 8 <= cnt; e += 8) {
        int s0 = bp[e + 0];
        int s1 = bp[e + 1];
        int s2 = bp[e + 2];
        int s3 = bp[e + 3];
        int s4 = bp[e + 4];
        int s5 = bp[e + 5];
        int s6 = bp[e + 6];
        int s7 = bp[e + 7];
        uint2 v0 = xh[(size_t)s0 * 32 + lane];
        uint2 v1 = xh[(size_t)s1 * 32 + lane];
        uint2 v2 = xh[(size_t)s2 * 32 + lane];
        uint2 v3 = xh[(size_t)s3 * 32 + lane];
        uint2 v4 = xh[(size_t)s4 * 32 + lane];
        uint2 v5 = xh[(size_t)s5 * 32 + lane];
        uint2 v6 = xh[(size_t)s6 * 32 + lane];
        uint2 v7 = xh[(size_t)s7 * 32 + lane];
        acc_half4(v0, ax, ay, az, aw); acc_half4(v1, ax, ay, az, aw);
        acc_half4(v2, ax, ay, az, aw); acc_half4(v3, ax, ay, az, aw);
        acc_half4(v4, ax, ay, az, aw); acc_half4(v5, ax, ay, az, aw);
        acc_half4(v6, ax, ay, az, aw); acc_half4(v7, ax, ay, az, aw);
    }
    for (; e < cnt; e++) {
        int s = bp[e];
        uint2 v = xh[(size_t)s * 32 + lane];
        acc_half4(v, ax, ay, az, aw);
    }
    float di = 1.0f / fmaxf((float)rawcnt, 1.0f);
    float4 r; r.x = ax * di; r.y = ay * di; r.z = az * di; r.w = aw * di;
    ((float4*)g_agg)[(size_t)w * 32 + lane] = r;
}

// -- layer 1: resident-weight dual GEMM + L2norm/relu + in-block projection ----
// 512 threads, 1 CTA/SM. Full W1_l/W1_r staged ONCE (stride-132, conflict-free
// LDS.128). A/X tiles double-buffered per warp via cp.async.
__global__ __launch_bounds__(512, 1) void k_gemm1p(const float* __restrict__ x,
                                                   const float* __restrict__ Wl,
                                                   const float* __restrict__ Wr,
                                                   const float* __restrict__ bias,
                                                   const float* __restrict__ W2l,
                                                   const float* __restrict__ W2r) {
    extern __shared__ __align__(16) float sm[];

    int tid = threadIdx.x;
    int rg = tid >> 5, cg = tid & 31;     // 16 warps, warp rg owns rows rg*8..+7
    int rowBase = blockIdx.x * 128;

    const float4* x4 = (const float4*)x;
    const float4* a4 = (const float4*)g_agg;
    const float4* wl4 = (const float4*)Wl;
    const float4* wr4 = (const float4*)Wr;

    // ---- stage full weights once (4096 float4 each) ----
    for (int t = tid; t < 4096; t += 512) {
        int j = t >> 5, c = t & 31;
        *(float4*)&sm[WL_OFF + j * 132 + c * 4] = wl4[t];
        *(float4*)&sm[WR_OFF + j * 132 + c * 4] = wr4[t];
    }

    ull acc[8][4];
#pragma unroll
    for (int c = 0; c < 4; c++) {
        ull b = (ull)__float_as_uint(bias[cg + 32 * c]);   // lo=bias, hi=0
#pragma unroll
        for (int i = 0; i < 8; i++) acc[i][c] = b;
    }

    // per-warp double buffer: 2 x (sA 128 | sX 128) floats
    float* axbuf = &sm[AX_OFF + rg * 512];
    unsigned axsh = (unsigned)__cvta_generic_to_shared(axbuf);
    int lr = cg >> 2, lc = cg & 3;         // lane -> (row, k-chunk) for staging
    int myrow = rowBase + rg * 8 + lr;     // < NPAD; g_agg pad rows are zeros
    int xvalid = (myrow < N_NODES) ? 16 : 0;
    unsigned laneoff = (unsigned)(lr * 64 + lc * 16);

    __syncthreads();                       // weights resident

    // prefetch kt=0
    cpa16(axsh + laneoff, &a4[(size_t)myrow * 32 + lc], 16);
    cpa16(axsh + 512 + laneoff, &x4[(size_t)myrow * 32 + lc], xvalid);
    CP_COMMIT();

    for (int kt = 0; kt < 8; kt++) {
        __syncwarp();                      // prior buffer reads done warp-wide
        if (kt < 7) {
            unsigned boff = ((kt + 1) & 1) * 1024;
            cpa16(axsh + boff + laneoff,
                  &a4[(size_t)myrow * 32 + (kt + 1) * 4 + lc], 16);
            cpa16(axsh + boff + 512 + laneoff,
                  &x4[(size_t)myrow * 32 + (kt + 1) * 4 + lc], xvalid);
            CP_COMMIT();
            CP_WAIT(1);                    // group kt complete
        } else {
            CP_WAIT(0);
        }
        __syncwarp();                      // all lanes' async writes visible

        const float* sA = axbuf + (kt & 1) * 256;
        const float* sX = sA + 128;
#pragma unroll
        for (int kp2 = 0; kp2 < 4; kp2++) {
            int ko = kt * 16 + kp2 * 4;
            ulonglong2 wl[4], wr[4];
#pragma unroll
            for (int c = 0; c < 4; c++) {
                wl[c] = *(const ulonglong2*)&sm[WL_OFF + (cg + 32 * c) * 132 + ko];
                wr[c] = *(const ulonglong2*)&sm[WR_OFF + (cg + 32 * c) * 132 + ko];
            }
#pragma unroll
            for (int i = 0; i < 8; i++) {
                ulonglong2 a  = *(const ulonglong2*)&sA[i * 16 + kp2 * 4];  // bcast
                ulonglong2 xx = *(const ulonglong2*)&sX[i * 16 + kp2 * 4];  // bcast
#pragma unroll
                for (int c = 0; c < 4; c++) {
                    FMA2(acc[i][c], a.x,  wl[c].x);
                    FMA2(acc[i][c], a.y,  wl[c].y);
                    FMA2(acc[i][c], xx.x, wr[c].x);
                    FMA2(acc[i][c], xx.y, wr[c].y);
                }
            }
        }
    }

    __syncthreads();   // all weight reads done; safe to overlay sH / sW2

    // stage combined proj weights C[96 x 128] (rows 0..39=W2l, 40..79=W2r, pad)
    {
        const float4* w2l4 = (const float4*)W2l;
        const float4* w2r4 = (const float4*)W2r;
        for (int t = tid; t < 96 * 32; t += 512) {
            int j = t >> 5, c = t & 31;
            float4 w = make_float4(0.f, 0.f, 0.f, 0.f);
            if (j < OUTD)          w = w2l4[j * 32 + c];
            else if (j < 2 * OUTD) w = w2r4[(j - OUTD) * 32 + c];
            *(float4*)&sm[W2_OFF + j * 132 + c * 4] = w;
        }
    }

    // epilogue: L2-normalize + relu; h rows are warp-private in sH (stride 132)
#pragma unroll
    for (int i = 0; i < 8; i++) {
        float v[4];
        float ss = 0.f;
#pragma unroll
        for (int c = 0; c < 4; c++) { v[c] = unpack_sum(acc[i][c]); ss += v[c] * v[c]; }
#pragma unroll
        for (int o = 16; o > 0; o >>= 1) ss += __shfl_xor_sync(0xffffffffu, ss, o);
        float scale = 1.0f / fmaxf(sqrtf(ss), EPSF);
#pragma unroll
        for (int c = 0; c < 4; c++)
            sm[SH_OFF + (rg * 8 + i) * 132 + cg + 32 * c] = fmaxf(v[c] * scale, 0.f);
    }

    __syncthreads();   // sW2 visible (sH rows stay warp-private)

    // in-block combined projection: [p | hr] = h @ C^T  (no syncs inside)
    ull pacc[8][3];
#pragma unroll
    for (int i = 0; i < 8; i++) {
        pacc[i][0] = 0ull; pacc[i][1] = 0ull; pacc[i][2] = 0ull;
    }
#pragma unroll
    for (int kt = 0; kt < 8; kt++) {
#pragma unroll
        for (int kp2 = 0; kp2 < 4; kp2++) {
            int ko = kt * 16 + kp2 * 4;
            ulonglong2 w0 = *(const ulonglong2*)&sm[W2_OFF + cg * 132 + ko];
            ulonglong2 w1 = *(const ulonglong2*)&sm[W2_OFF + (cg + 32) * 132 + ko];
            ulonglong2 w2 = *(const ulonglong2*)&sm[W2_OFF + (cg + 64) * 132 + ko];
#pragma unroll
            for (int i = 0; i < 8; i++) {
                ulonglong2 a = *(const ulonglong2*)&sm[SH_OFF + (rg * 8 + i) * 132 + ko];
                FMA2(pacc[i][0], a.x, w0.x); FMA2(pacc[i][0], a.y, w0.y);
                FMA2(pacc[i][1], a.x, w1.x); FMA2(pacc[i][1], a.y, w1.y);
                FMA2(pacc[i][2], a.x, w2.x); FMA2(pacc[i][2], a.y, w2.y);
            }
        }
    }
#pragma unroll
    for (int i = 0; i < 8; i++) {
        int row = rowBase + rg * 8 + i;      // < NPAD always
#pragma unroll
        for (int c = 0; c < 3; c++) {
            int jc = cg + 32 * c;
            float val = unpack_sum(pacc[i][c]);
            if (jc < OUTD)            g_p[(size_t)row * OUTD + jc] = __float2half(val);
            else if (jc < 2 * OUTD)   g_hr[(size_t)row * OUTD + (jc - OUTD)] = val;
        }
    }
}

// ---- fused layer-2 tail: gather p(fp16) -> mean -> +b2+hr -> norm/relu/logsm --
__global__ void k_aggfinal(const float* __restrict__ bias,
                           float* __restrict__ out) {
    int gt = blockIdx.x * blockDim.x + threadIdx.x;
    int w = gt >> 5, lane = gt & 31;
    if (w >= N_NODES) return;
    bool valid = lane < 20;
    float sx = 0.f, sy = 0.f;
    if (valid) {
        const __half2* p2 = (const __half2*)g_p;   // 20 half2 per row
        int rawcnt = g_cnt[w];
        int cnt = min(rawcnt, BCAP);
        const int* bp = &g_bkt[(size_t)w * BCAP];
        int e = 0;
        for (; e + 8 <= cnt; e += 8) {
            int s0 = bp[e + 0];
            int s1 = bp[e + 1];
            int s2 = bp[e + 2];
            int s3 = bp[e + 3];
            int s4 = bp[e + 4];
            int s5 = bp[e + 5];
            int s6 = bp[e + 6];
            int s7 = bp[e + 7];
            float2 v0 = __half22float2(p2[(size_t)s0 * 20 + lane]);
            float2 v1 = __half22float2(p2[(size_t)s1 * 20 + lane]);
            float2 v2 = __half22float2(p2[(size_t)s2 * 20 + lane]);
            float2 v3 = __half22float2(p2[(size_t)s3 * 20 + lane]);
            float2 v4 = __half22float2(p2[(size_t)s4 * 20 + lane]);
            float2 v5 = __half22float2(p2[(size_t)s5 * 20 + lane]);
            float2 v6 = __half22float2(p2[(size_t)s6 * 20 + lane]);
            float2 v7 = __half22float2(p2[(size_t)s7 * 20 + lane]);
            sx += (v0.x + v1.x) + (v2.x + v3.x) + ((v4.x + v5.x) + (v6.x + v7.x));
            sy += (v0.y + v1.y) + (v2.y + v3.y) + ((v4.y + v5.y) + (v6.y + v7.y));
        }
        for (; e < cnt; e++) {
            int s = bp[e];
            float2 v = __half22float2(p2[(size_t)s * 20 + lane]);
            sx += v.x; sy += v.y;
        }
        float di = 1.0f / fmaxf((float)rawcnt, 1.0f);
        float2 h = ((const float2*)g_hr)[(size_t)w * 20 + lane];
        float2 b = ((const float2*)bias)[lane];
        sx = sx * di + b.x + h.x;
        sy = sy * di + b.y + h.y;
    }
    float ss = sx * sx + sy * sy;
#pragma unroll
    for (int o = 16; o > 0; o >>= 1) ss += __shfl_xor_sync(0xffffffffu, ss, o);
    float scale = 1.0f / fmaxf(sqrtf(ss), EPSF);
    sx = fmaxf(sx * scale, 0.f);
    sy = fmaxf(sy * scale, 0.f);
    float m = valid ? fmaxf(sx, sy) : -3.0e38f;
#pragma unroll
    for (int o = 16; o > 0; o >>= 1) m = fmaxf(m, __shfl_xor_sync(0xffffffffu, m, o));
    float p = valid ? (expf(sx - m) + expf(sy - m)) : 0.f;
#pragma unroll
    for (int o = 16; o > 0; o >>= 1) p += __shfl_xor_sync(0xffffffffu, p, o);
    float lse = m + logf(p);
    if (valid) {
        float2 o2 = make_float2(sx - lse, sy - lse);
        *(float2*)&out[(size_t)w * OUTD + 2 * lane] = o2;
    }
}

// ------------------------- launcher -------------------------------------------
extern "C" void kernel_launch(void* const* d_in, const int* in_sizes, int n_in,
                              void* d_out, int out_size) {
    const float* x   = (const float*)d_in[0];
    const void*  ei  = d_in[1];
    const float* W1l = (const float*)d_in[2];
    const float* b1  = (const float*)d_in[3];
    const float* W1r = (const float*)d_in[4];
    const float* W2l = (const float*)d_in[5];
    const float* b2  = (const float*)d_in[6];
    const float* W2r = (const float*)d_in[7];
    float* out = (float*)d_out;

    cudaFuncSetAttribute(k_gemm1p, cudaFuncAttributeMaxDynamicSharedMemorySize,
                         SMEM_BYTES);

    // prep: zero counters + dtype detect, fp16 copy of x, bucket scatter
    k_init<<<(N_NODES + 255) / 256, 256>>>((const unsigned*)ei);
    k_tohalf<<<(N_NODES * 32 + 255) / 256, 256>>>((const float4*)x);
    k_bucket<<<(N_EDGES + 255) / 256, 256>>>(ei);

    // layer 1: fp16 gather-agg -> resident-weight dual gemm with fused proj
    k_agg<<<(N_NODES * 32 + 255) / 256, 256>>>();
    k_gemm1p<<<GEMM_BLOCKS, 512, SMEM_BYTES>>>(x, W1l, W1r, b1, W2l, W2r);

    // layer 2 tail: fused fp16 gather + epilogue
    k_aggfinal<<<(N_NODES * 32 + 255) / 256, 256>>>(b2, out);
}